// round 6
// baseline (speedup 1.0000x reference)
#include <cuda_runtime.h>
#include <cuda_bf16.h>

// End2EndRVFixedOutput_TRT fixed-output ragged copy.
// Inputs (metadata order):
//   d_in[0] = num_dets : int32 [B]          (B = 8, values in [0, 12))
//   d_in[1] = boxes    : float32 [B, N, 4]  (N = 8192)
//   d_in[2] = scores   : float32 [B, N]
//   d_in[3] = classes  : float32 [B, N]
// Output: float32 [100, 7], columns = [batch_id, box0..3, class, score]
//
// Semantics: for n = 0..B-1 in order (later overwrites earlier):
//   off = (n == 0) ? 0 : num_dets[n-1];  k = num_dets[n]
//   out[off : off+k] = [n, boxes[n,0:k], classes[n,0:k], scores[n,0:k]]
// Uncovered rows are zero.
//
// Key facts exploited:
//  - num_dets < 12  =>  off <= 11, k <= 11  =>  only rows 0..21 can ever be
//    covered. Rows 22..99 (546 of 700 elements) are unconditionally zero and
//    are stored BEFORE the barrier, fully overlapped with the DRAM latency of
//    the prefetch loads.
//  - All possibly-needed source data (src < 11) is prefetched into shared in
//    parallel with the num_dets load (one exposed DRAM latency total).

#define OUT_ROWS 100
#define OUT_COLS 7
#define NB 8              // batch count (fixed by problem shape)
#define KMAX 11           // num_dets < 12  =>  src <= 10
#define LIVE_ELEMS (22 * OUT_COLS)   // 154: only rows < 22 can be nonzero
#define NTHREADS 256      // 8 warps; 184 prefetch slots + zero-store coverage

__global__ void __launch_bounds__(NTHREADS, 1)
e2e_fixed_output_kernel(const int* __restrict__ num_dets,
                        const float* __restrict__ boxes,
                        const float* __restrict__ scores,
                        const float* __restrict__ classes,
                        float* __restrict__ out,
                        int N) {
    __shared__ int    s_nd[NB];
    __shared__ float4 s_box[NB * KMAX];   // boxes[n, src, 0:4]
    __shared__ float  s_cls[NB * KMAX];   // classes[n, src]
    __shared__ float  s_scr[NB * KMAX];   // scores[n, src]

    const int t = threadIdx.x;

    // ---- Phase 1a: issue all prefetch loads (independent, high MLP) ----
    if (t < NB) {
        s_nd[t] = num_dets[t];
    } else if (t < NB + NB * KMAX) {
        int i = t - NB;                                   // 0..87
        int n = i / KMAX, src = i % KMAX;
        s_box[i] = *reinterpret_cast<const float4*>(boxes + ((size_t)n * N + src) * 4);
    } else if (t < NB + 2 * NB * KMAX) {                  // t in [96, 184)
        int i = t - (NB + NB * KMAX);
        int n = i / KMAX, src = i % KMAX;
        // Two independent loads per thread; both overlap the DRAM wait.
        s_cls[i] = classes[(size_t)n * N + src];
        s_scr[i] = scores[(size_t)n * N + src];
    }

    // ---- Phase 1b: zero stores for always-zero elements, overlapped with
    //      the in-flight prefetch loads (no dependency on them). ----
    for (int e = LIVE_ELEMS + t; e < OUT_ROWS * OUT_COLS; e += NTHREADS)
        out[e] = 0.0f;

    __syncthreads();

    // ---- Phase 2: resolve the 154 potentially-live elements from shared ----
    if (t >= LIVE_ELEMS) return;

    const int r = t / OUT_COLS;   // 0..21
    const int c = t % OUT_COLS;

    float val = 0.0f;
    // Largest covering n wins (later batches overwrite earlier rows).
    #pragma unroll
    for (int n = NB - 1; n >= 0; --n) {
        const int off = (n == 0) ? 0 : s_nd[n - 1];
        const int k   = s_nd[n];
        if (r >= off && r < off + k) {
            const int src = r - off;          // < k <= KMAX, in-bounds by mask
            const int i   = n * KMAX + src;
            if (c == 0)      val = (float)n;
            else if (c <= 4) val = (&s_box[i].x)[c - 1];
            else if (c == 5) val = s_cls[i];
            else             val = s_scr[i];
            break;
        }
    }
    out[t] = val;
}

extern "C" void kernel_launch(void* const* d_in, const int* in_sizes, int n_in,
                              void* d_out, int out_size) {
    const int*   num_dets = (const int*)d_in[0];
    const float* boxes    = (const float*)d_in[1];
    const float* scores   = (const float*)d_in[2];
    const float* classes  = (const float*)d_in[3];
    float*       out      = (float*)d_out;

    const int B = in_sizes[0];          // 8
    const int N = in_sizes[2] / B;      // 8192

    e2e_fixed_output_kernel<<<1, NTHREADS>>>(num_dets, boxes, scores, classes, out, N);
}

// round 7
// speedup vs baseline: 1.7981x; 1.7981x over previous
#include <cuda_runtime.h>
#include <cuda_bf16.h>

// End2EndRVFixedOutput_TRT fixed-output ragged copy.
// Inputs (metadata order):
//   d_in[0] = num_dets : int32 [B]          (B = 8, values in [0, 12))
//   d_in[1] = boxes    : float32 [B, N, 4]  (N = 8192)
//   d_in[2] = scores   : float32 [B, N]
//   d_in[3] = classes  : float32 [B, N]
// Output: float32 [100, 7], columns = [batch_id, box0..3, class, score]
//
// Semantics: for n = 0..B-1 in order (later overwrites earlier):
//   off = (n == 0) ? 0 : num_dets[n-1];  k = num_dets[n]
//   out[off : off+k] = [n, boxes[n,0:k], classes[n,0:k], scores[n,0:k]]
// Uncovered rows are zero.
//
// Design (single exposed DRAM latency):
//  - num_dets < 12  =>  off <= 11, k <= 11  =>  only rows 0..21 can be
//    covered. The 546 elements of rows 22..99 are unconditionally zero and
//    stored BEFORE the barrier (one STG per thread, no loop), fully
//    overlapped with the prefetch loads' DRAM latency.
//  - All possibly-needed source data (src < 11, 8 batches) is prefetched
//    into shared in parallel with the num_dets load.

#define OUT_ROWS 100
#define OUT_COLS 7
#define NB 8                          // batch count (fixed by problem shape)
#define KMAX 11                       // num_dets < 12  =>  src <= 10
#define LIVE_ELEMS (22 * OUT_COLS)    // 154: only rows < 22 can be nonzero
#define NTHREADS 704                  // 22 warps: 1 output element per thread

__global__ void __launch_bounds__(NTHREADS, 1)
e2e_fixed_output_kernel(const int* __restrict__ num_dets,
                        const float* __restrict__ boxes,
                        const float* __restrict__ scores,
                        const float* __restrict__ classes,
                        float* __restrict__ out,
                        int N) {
    __shared__ int    s_nd[NB];
    __shared__ float4 s_box[NB * KMAX];   // boxes[n, src, 0:4]
    __shared__ float  s_cls[NB * KMAX];   // classes[n, src]
    __shared__ float  s_scr[NB * KMAX];   // scores[n, src]

    const int t = threadIdx.x;

    // ---- Phase 1a: issue all prefetch loads (independent, high MLP) ----
    if (t < NB) {
        s_nd[t] = num_dets[t];
    } else if (t < NB + NB * KMAX) {
        int i = t - NB;                                   // 0..87
        int n = i / KMAX, src = i % KMAX;
        s_box[i] = *reinterpret_cast<const float4*>(boxes + ((size_t)n * N + src) * 4);
    } else if (t < NB + 2 * NB * KMAX) {                  // t in [96, 184)
        int i = t - (NB + NB * KMAX);
        int n = i / KMAX, src = i % KMAX;
        // Two independent loads per thread; both overlap the DRAM wait.
        s_cls[i] = classes[(size_t)n * N + src];
        s_scr[i] = scores[(size_t)n * N + src];
    }

    // ---- Phase 1b: unconditional-zero elements stored pre-barrier,
    //      overlapped with the in-flight prefetch loads (no dependency). ----
    if (t >= LIVE_ELEMS && t < OUT_ROWS * OUT_COLS)
        out[t] = 0.0f;

    __syncthreads();

    // ---- Phase 2: resolve the 154 potentially-live elements from shared ----
    if (t >= LIVE_ELEMS) return;

    const int r = t / OUT_COLS;   // 0..21
    const int c = t % OUT_COLS;

    float val = 0.0f;
    // Largest covering n wins (later batches overwrite earlier rows).
    #pragma unroll
    for (int n = NB - 1; n >= 0; --n) {
        const int off = (n == 0) ? 0 : s_nd[n - 1];
        const int k   = s_nd[n];
        if (r >= off && r < off + k) {
            const int src = r - off;          // < k <= KMAX, in-bounds by mask
            const int i   = n * KMAX + src;
            if (c == 0)      val = (float)n;
            else if (c <= 4) val = (&s_box[i].x)[c - 1];
            else if (c == 5) val = s_cls[i];
            else             val = s_scr[i];
            break;
        }
    }
    out[t] = val;
}

extern "C" void kernel_launch(void* const* d_in, const int* in_sizes, int n_in,
                              void* d_out, int out_size) {
    const int*   num_dets = (const int*)d_in[0];
    const float* boxes    = (const float*)d_in[1];
    const float* scores   = (const float*)d_in[2];
    const float* classes  = (const float*)d_in[3];
    float*       out      = (float*)d_out;

    const int B = in_sizes[0];          // 8
    const int N = in_sizes[2] / B;      // 8192

    e2e_fixed_output_kernel<<<1, NTHREADS>>>(num_dets, boxes, scores, classes, out, N);
}